// round 14
// baseline (speedup 1.0000x reference)
#include <cuda_runtime.h>
#include <cuda_bf16.h>
#include <math.h>
#include <stdint.h>
#include <string.h>

#define E   128
#define KC  12
#define BV  4096
#define RD  65536
#define NTILES 512

#define LOG2PI  1.8378770664093453f
#define SQRT2C  1.4142135623730951f
#define SQRTPI  1.7724538509055159f

// ---------------- device globals ----------------
__device__ uint32_t g_BH[9216];   // B-high fragments, smem-identical layout
__device__ uint32_t g_BL[9216];   // B-low  fragments
__device__ float    g_kon[84];
__device__ float    g_lsm[KC];
__device__ float    g_sig2[E];
__device__ float    g_slog;

// ---------------- helpers ----------------
__device__ __forceinline__ uint32_t smem_u32(const void* p){
    uint32_t a;
    asm("{ .reg .u64 t; cvta.to.shared.u64 t, %1; cvt.u32.u64 %0, t; }" : "=r"(a) : "l"(p));
    return a;
}
#define LDS128(r0,r1,r2,r3,addr) \
    asm volatile("ld.shared.v4.b32 {%0,%1,%2,%3}, [%4];" \
        : "=r"(r0),"=r"(r1),"=r"(r2),"=r"(r3) : "r"(addr))
#define STS64F(addr,v0,v1) \
    asm volatile("st.shared.v2.f32 [%0], {%1,%2};" :: "r"(addr), "f"(v0), "f"(v1))
#define STS128(addr,r0,r1,r2,r3) \
    asm volatile("st.shared.v4.b32 [%0], {%1,%2,%3,%4};" \
        :: "r"(addr), "r"(r0),"r"(r1),"r"(r2),"r"(r3))

__device__ __forceinline__ void mma_bf16(float* d, uint32_t a0, uint32_t a1,
                                         uint32_t a2, uint32_t a3,
                                         uint32_t b0, uint32_t b1){
    asm("mma.sync.aligned.m16n8k16.row.col.f32.bf16.bf16.f32 "
        "{%0,%1,%2,%3}, {%4,%5,%6,%7}, {%8,%9}, {%0,%1,%2,%3};"
        : "+f"(d[0]), "+f"(d[1]), "+f"(d[2]), "+f"(d[3])
        : "r"(a0), "r"(a1), "r"(a2), "r"(a3), "r"(b0), "r"(b1));
}

__device__ __forceinline__ void split2(float v0, float v1, uint32_t& hb, uint32_t& lb){
    __nv_bfloat162 h = __float22bfloat162_rn(make_float2(v0, v1));
    float l0 = v0 - __bfloat162float(h.x);
    float l1 = v1 - __bfloat162float(h.y);
    __nv_bfloat162 lo = __float22bfloat162_rn(make_float2(l0, l1));
    memcpy(&hb, &h, 4);
    memcpy(&lb, &lo, 4);
}

// ---------------- K1: one-block setup (consts + P + global B) ----------------
__global__ void __launch_bounds__(512,1)
setup_kernel(const float* __restrict__ rot,
             const float* __restrict__ stde,
             const float* __restrict__ dirs,
             const float* __restrict__ mu,
             const float* __restrict__ sig,
             const float* __restrict__ lam,
             const float* __restrict__ asd,
             const float* __restrict__ w)
{
    __shared__ float DIRSs[KC*E];
    __shared__ float Ps[E*KC];
    __shared__ float INVs[E];
    __shared__ float REDs[4];
    const int tid = threadIdx.x, wid = tid>>5, lane = tid&31;
    const unsigned full = 0xffffffffu;

    for (int i=tid; i<KC*E; i+=512) DIRSs[i] = dirs[i];

    float lv = 0.f;
    if (tid < E){
        float s = stde[tid];
        INVs[tid]   = 1.f/s;
        g_sig2[tid] = s*s;
        lv = logf(s);
    }
    #pragma unroll
    for (int o=16;o>0;o>>=1) lv += __shfl_xor_sync(full, lv, o);
    if (tid < E && lane==0) REDs[wid] = lv;

    if (tid < KC){
        float m=mu[tid], s_=sig[tid], l=lam[tid], a=asd[tid];
        float A = m + l*s_*s_;
        g_kon[tid]    = A;
        g_kon[12+tid] = m + A;
        g_kon[24+tid] = 1.f/(SQRT2C*s_);
        g_kon[36+tid] = logf(0.5f*l);
        g_kon[48+tid] = 0.5f*l;
        g_kon[60+tid] = -0.5f*(float)(E-1)*LOG2PI - (float)(E-1)*logf(a);
        g_kon[72+tid] = 1.f/(2.f*a*a);
    }
    if (tid >= 32 && tid < 64){
        int t = tid - 32;
        float v = (t < KC) ? w[t] : -1e30f;
        float m = v;
        #pragma unroll
        for (int o=8;o>0;o>>=1) m = fmaxf(m, __shfl_xor_sync(full, m, o));
        float e = (t < KC) ? expf(v-m) : 0.f;
        #pragma unroll
        for (int o=8;o>0;o>>=1) e += __shfl_xor_sync(full, e, o);
        if (t < KC) g_lsm[t] = v - (m + logf(e));
    }
    __syncthreads();
    if (tid==0) g_slog = REDs[0]+REDs[1]+REDs[2]+REDs[3];

    // P[e][k] = (Rot^T dirs_k)[e] / ||dirs_k||
    {
        const int gg = tid>>7, e = tid&127;
        float p0=0.f, p1=0.f, p2=0.f;
        float n0=0.f, n1=0.f, n2=0.f;
        const float* d0 = DIRSs + (gg*3+0)*E;
        const float* d1 = DIRSs + (gg*3+1)*E;
        const float* d2 = DIRSs + (gg*3+2)*E;
        #pragma unroll 16
        for (int j=0; j<E; j++){
            float rv = __ldg(rot + j*E + e);
            float a0 = d0[j], a1 = d1[j], a2 = d2[j];
            p0 = fmaf(rv, a0, p0);  n0 = fmaf(a0, a0, n0);
            p1 = fmaf(rv, a1, p1);  n1 = fmaf(a1, a1, n1);
            p2 = fmaf(rv, a2, p2);  n2 = fmaf(a2, a2, n2);
        }
        Ps[e*12 + gg*3    ] = p0 * rsqrtf(n0);
        Ps[e*12 + gg*3 + 1] = p1 * rsqrtf(n1);
        Ps[e*12 + gg*3 + 2] = p2 * rsqrtf(n2);
    }
    __syncthreads();

    // B fill into PAIRED fragment layout, stored to GLOBAL
    #pragma unroll
    for (int it=0; it<18; it++){
        int p = tid + it*512;
        int n = p>>6, k = (p&63)*2;
        float v0, v1;
        if (n < 128){
            float is = INVs[n];
            v0 = __ldg(rot + n*E+k)*is; v1 = __ldg(rot + n*E+k+1)*is;
        } else if (n < 140){
            int kc = n-128;
            v0 = Ps[k*KC + kc]; v1 = Ps[(k+1)*KC + kc];
        } else { v0 = 0.f; v1 = 0.f; }
        uint32_t hb, lb;
        split2(v0, v1, hb, lb);
        int nb = n>>3;
        int hfb = (nb >= 9);
        int nbl = nb - 9*hfb;
        int l  = (n&7)*4 + ((k&7)>>1);
        int jB = (k>>3)&1;
        int kb = k>>4;
        uint32_t byteB;
        if (nbl < 8){
            int i = nbl>>1, which = nbl&1;
            byteB = (uint32_t)(hfb*18432 + i*4096 + kb*512 + l*16 + which*8 + jB*4);
        } else {
            byteB = (uint32_t)(hfb*18432 + 16384 + kb*256 + l*8 + jB*4);
        }
        g_BH[byteB>>2] = hb;
        g_BL[byteB>>2] = lb;
    }
}

// ---------------- K2: one tile per 256-thread CTA (3 CTAs/SM) ----------------
#define A_L_OFF  32768
#define OFF_DOT  65536     // 128 x 12 f32 = 6144
#define OFF_S2B  71680     // 2 x 128 f32 = 1024
#define OFF_NXB  72704     // 1024
#define OFF_SIG2 73728     // 512
#define OFF_T    74240     // 512
#define OFF_KON  74752     // 336
#define OFF_LSM  75088     // 48
#define SMEM_BYTES 75136

__global__ void __launch_bounds__(256)
main_kernel(const float* __restrict__ alt,
            const float* __restrict__ trans,
            float* __restrict__ out)
{
    extern __shared__ char sm[];
    const uint32_t smb = smem_u32(sm);
    const int tid = threadIdx.x, wid = tid>>5, lane = tid&31;
    const int lq = lane>>2, lr = lane&3;
    const unsigned full = 0xffffffffu;
    float* SIG2f = (float*)(sm + OFF_SIG2);
    float* Tf    = (float*)(sm + OFF_T);
    float* KON   = (float*)(sm + OFF_KON);
    float* DOTf  = (float*)(sm + OFF_DOT);
    float* S2Bf  = (float*)(sm + OFF_S2B);
    float* NXBf  = (float*)(sm + OFF_NXB);
    float* LSM   = (float*)(sm + OFF_LSM);

    // tiny const prologue
    if (tid < E){ SIG2f[tid] = g_sig2[tid]; Tf[tid] = trans[tid]; }
    if (tid >= 128 && tid < 212) KON[tid-128] = g_kon[tid-128];
    if (tid >= 212 && tid < 224) LSM[tid-212] = g_lsm[tid-212];
    const float slog = g_slog;
    __syncthreads();

    const int tile = blockIdx.x;
    const int ms = wid&3, hf = wid>>2;

    // ---- convert: warp wid handles rows wid*16..+15
    {
        const float2* a2 = (const float2*)alt;
        const uint32_t convBase = smb + (uint32_t)(wid*4096 + lane*16);
        const int row0 = tile*128 + wid*16 + lq;
        #pragma unroll
        for (int kb=0; kb<8; kb++){
            int c0 = kb*16 + 2*lr, c1 = c0 + 8;
            float2 v00 = a2[(size_t)row0*64     + (c0>>1)];
            float2 v10 = a2[(size_t)(row0+8)*64 + (c0>>1)];
            float2 v01 = a2[(size_t)row0*64     + (c1>>1)];
            float2 v11 = a2[(size_t)(row0+8)*64 + (c1>>1)];
            float2 t0 = *(const float2*)(Tf + c0);
            float2 t1 = *(const float2*)(Tf + c1);
            uint32_t h0,l0,h1,l1,h2,l2,h3,l3;
            split2(v00.x+t0.x, v00.y+t0.y, h0, l0);
            split2(v10.x+t0.x, v10.y+t0.y, h1, l1);
            split2(v01.x+t1.x, v01.y+t1.y, h2, l2);
            split2(v11.x+t1.x, v11.y+t1.y, h3, l3);
            STS128(convBase + kb*512,           h0,h1,h2,h3);
            STS128(convBase + A_L_OFF + kb*512, l0,l1,l2,l3);
        }
    }
    __syncthreads();

    // ---- MMA: B fragments via LDG from global (L2-resident, coalesced)
    const uint32_t aBase = smb + (uint32_t)(ms*8192 + lane*16);
    const uint4* bPairH = (const uint4*)g_BH + (hf*1152 + lane);
    const uint4* bPairL = (const uint4*)g_BL + (hf*1152 + lane);
    const uint2* b8H    = (const uint2*)g_BH + (hf*2304 + 2048 + lane);
    const uint2* b8L    = (const uint2*)g_BL + (hf*2304 + 2048 + lane);

    float acc0[9][4], acc1[9][4];
    #pragma unroll
    for (int i=0;i<9;i++){
        acc0[i][0]=0.f;acc0[i][1]=0.f;acc0[i][2]=0.f;acc0[i][3]=0.f;
        acc1[i][0]=0.f;acc1[i][1]=0.f;acc1[i][2]=0.f;acc1[i][3]=0.f;
    }
    #pragma unroll
    for (int kb=0; kb<8; kb++){
        uint32_t ah0[4], ah1[4], al0[4], al1[4];
        LDS128(ah0[0],ah0[1],ah0[2],ah0[3], aBase + kb*512);
        LDS128(ah1[0],ah1[1],ah1[2],ah1[3], aBase + 4096 + kb*512);
        LDS128(al0[0],al0[1],al0[2],al0[3], aBase + A_L_OFF + kb*512);
        LDS128(al1[0],al1[1],al1[2],al1[3], aBase + A_L_OFF + 4096 + kb*512);
        #pragma unroll
        for (int i=0; i<4; i++){
            uint4 bh = __ldg(bPairH + i*256 + kb*32);
            uint4 bl = __ldg(bPairL + i*256 + kb*32);
            mma_bf16(acc0[2*i  ], ah0[0],ah0[1],ah0[2],ah0[3], bh.x,bh.y);
            mma_bf16(acc1[2*i  ], ah1[0],ah1[1],ah1[2],ah1[3], bh.x,bh.y);
            mma_bf16(acc0[2*i  ], al0[0],al0[1],al0[2],al0[3], bh.x,bh.y);
            mma_bf16(acc1[2*i  ], al1[0],al1[1],al1[2],al1[3], bh.x,bh.y);
            mma_bf16(acc0[2*i  ], ah0[0],ah0[1],ah0[2],ah0[3], bl.x,bl.y);
            mma_bf16(acc1[2*i  ], ah1[0],ah1[1],ah1[2],ah1[3], bl.x,bl.y);
            mma_bf16(acc0[2*i+1], ah0[0],ah0[1],ah0[2],ah0[3], bh.z,bh.w);
            mma_bf16(acc1[2*i+1], ah1[0],ah1[1],ah1[2],ah1[3], bh.z,bh.w);
            mma_bf16(acc0[2*i+1], al0[0],al0[1],al0[2],al0[3], bh.z,bh.w);
            mma_bf16(acc1[2*i+1], al1[0],al1[1],al1[2],al1[3], bh.z,bh.w);
            mma_bf16(acc0[2*i+1], ah0[0],ah0[1],ah0[2],ah0[3], bl.z,bl.w);
            mma_bf16(acc1[2*i+1], ah1[0],ah1[1],ah1[2],ah1[3], bl.z,bl.w);
        }
        {
            uint2 bh = __ldg(b8H + kb*32);
            uint2 bl = __ldg(b8L + kb*32);
            mma_bf16(acc0[8], ah0[0],ah0[1],ah0[2],ah0[3], bh.x,bh.y);
            mma_bf16(acc1[8], ah1[0],ah1[1],ah1[2],ah1[3], bh.x,bh.y);
            mma_bf16(acc0[8], al0[0],al0[1],al0[2],al0[3], bh.x,bh.y);
            mma_bf16(acc1[8], al1[0],al1[1],al1[2],al1[3], bh.x,bh.y);
            mma_bf16(acc0[8], ah0[0],ah0[1],ah0[2],ah0[3], bl.x,bl.y);
            mma_bf16(acc1[8], ah1[0],ah1[1],ah1[2],ah1[3], bl.x,bl.y);
        }
    }

    // ---- extract: s2/nx partials + dot columns
    float s2v[4]={0.f,0.f,0.f,0.f}, nxv[4]={0.f,0.f,0.f,0.f};
    #pragma unroll
    for (int nb=0; nb<9; nb++){
        int col = hf*72 + nb*8 + 2*lr;
        if (hf==0 || nb<7){
            float g0 = SIG2f[col], g1 = SIG2f[col+1];
            float q;
            q = acc0[nb][0]*acc0[nb][0]; s2v[0]+=q; nxv[0]=fmaf(q,g0,nxv[0]);
            q = acc0[nb][1]*acc0[nb][1]; s2v[0]+=q; nxv[0]=fmaf(q,g1,nxv[0]);
            q = acc0[nb][2]*acc0[nb][2]; s2v[1]+=q; nxv[1]=fmaf(q,g0,nxv[1]);
            q = acc0[nb][3]*acc0[nb][3]; s2v[1]+=q; nxv[1]=fmaf(q,g1,nxv[1]);
            q = acc1[nb][0]*acc1[nb][0]; s2v[2]+=q; nxv[2]=fmaf(q,g0,nxv[2]);
            q = acc1[nb][1]*acc1[nb][1]; s2v[2]+=q; nxv[2]=fmaf(q,g1,nxv[2]);
            q = acc1[nb][2]*acc1[nb][2]; s2v[3]+=q; nxv[3]=fmaf(q,g0,nxv[3]);
            q = acc1[nb][3]*acc1[nb][3]; s2v[3]+=q; nxv[3]=fmaf(q,g1,nxv[3]);
        } else {
            int kc = (nb-7)*8 + 2*lr;
            if (kc < 12){
                int r0 = ms*32 + lq;
                uint32_t dbase = smb + OFF_DOT;
                STS64F(dbase + (uint32_t)((r0   )*48 + kc*4), acc0[nb][0], acc0[nb][1]);
                STS64F(dbase + (uint32_t)((r0+ 8)*48 + kc*4), acc0[nb][2], acc0[nb][3]);
                STS64F(dbase + (uint32_t)((r0+16)*48 + kc*4), acc1[nb][0], acc1[nb][1]);
                STS64F(dbase + (uint32_t)((r0+24)*48 + kc*4), acc1[nb][2], acc1[nb][3]);
            }
        }
    }
    #pragma unroll
    for (int o=1;o<4;o<<=1){
        #pragma unroll
        for (int i=0;i<4;i++){
            s2v[i] += __shfl_xor_sync(full, s2v[i], o);
            nxv[i] += __shfl_xor_sync(full, nxv[i], o);
        }
    }
    {
        float sv = (lr==0)?s2v[0]:(lr==1)?s2v[1]:(lr==2)?s2v[2]:s2v[3];
        float nv = (lr==0)?nxv[0]:(lr==1)?nxv[1]:(lr==2)?nxv[2]:nxv[3];
        int row = ms*32 + lr*8 + lq;
        S2Bf[hf*128 + row] = sv;
        NXBf[hf*128 + row] = nv;
    }
    __syncthreads();

    // ---- epilogue + in-warp segment reduction (warp = 1 variant of 16 reads)
    {
        const int r = tid>>1, h = tid&1;
        float s2 = S2Bf[r] + S2Bf[128 + r];
        float nx = NXBf[r] + NXBf[128 + r];
        float nonart = -64.f*LOG2PI - slog - 0.5f*s2;
        const float* drow = DOTf + r*12;
        float art[6];
        #pragma unroll
        for (int kk=0; kk<6; kk++){
            int k = h*6 + kk;
            float dk    = drow[k];
            float orth2 = nx - dk*dk;
            float oll   = KON[60+k] - orth2*KON[72+k];
            float z     = (KON[k] - dk)*KON[24+k];
            float lec;
            if (z > 5.f){
                float z2=z*z, z4=z2*z2, z6=z4*z2;
                lec = -z2 - logf(z*SQRTPI)
                      + log1pf(-1.f/(2.f*z2) + 3.f/(4.f*z4) - 15.f/(8.f*z6));
            } else {
                lec = logf(erfcf(z));
            }
            float par = KON[36+k] + lec + KON[48+k]*(KON[12+k] - 2.f*dk);
            art[kk] = oll + par;
        }
        #pragma unroll
        for (int o=2; o<32; o<<=1){
            nonart += __shfl_xor_sync(full, nonart, o);
            #pragma unroll
            for (int kk=0; kk<6; kk++)
                art[kk] += __shfl_xor_sync(full, art[kk], o);
        }
        float vmax = -1e30f, vsum = 0.f;
        float av[6];
        #pragma unroll
        for (int kk=0; kk<6; kk++){
            av[kk] = art[kk] + LSM[h*6 + kk];
            vmax = fmaxf(vmax, av[kk]);
        }
        #pragma unroll
        for (int kk=0; kk<6; kk++) vsum += expf(av[kk] - vmax);
        float m_o = __shfl_xor_sync(full, vmax, 1);
        float s_o = __shfl_xor_sync(full, vsum, 1);
        float M = fmaxf(vmax, m_o);
        float S = vsum*expf(vmax-M) + s_o*expf(m_o-M);
        float lse = M + logf(S);

        if (lane < 2){
            const int b = tile*8 + wid;
            if (h == 0){
                float logits = lse - nonart;
                out[b] = 20.f*tanhf(logits*(1.f/20.f));
                out[BV + b*(KC+1)] = nonart;
                #pragma unroll
                for (int kk=0; kk<6; kk++)
                    out[BV + b*(KC+1) + 1 + kk] = av[kk];
            } else {
                #pragma unroll
                for (int kk=0; kk<6; kk++)
                    out[BV + b*(KC+1) + 7 + kk] = av[kk];
            }
        }
    }
}

// ---------------- launch ----------------
extern "C" void kernel_launch(void* const* d_in, const int* in_sizes, int n_in,
                              void* d_out, int out_size)
{
    const float* alt   = (const float*)d_in[0];
    // d_in[1] = ref_re: unused by the reference output
    const float* trans = (const float*)d_in[2];
    const float* rot   = (const float*)d_in[3];
    const float* stde  = (const float*)d_in[4];
    const float* dirs  = (const float*)d_in[5];
    const float* mu    = (const float*)d_in[6];
    const float* sig   = (const float*)d_in[7];
    const float* lam   = (const float*)d_in[8];
    const float* asd   = (const float*)d_in[9];
    const float* w     = (const float*)d_in[10];
    float* out = (float*)d_out;

    cudaFuncSetAttribute(main_kernel, cudaFuncAttributeMaxDynamicSharedMemorySize,
                         SMEM_BYTES);

    setup_kernel<<<1, 512>>>(rot, stde, dirs, mu, sig, lam, asd, w);
    main_kernel<<<NTILES, 256, SMEM_BYTES>>>(alt, trans, out);
}

// round 15
// speedup vs baseline: 1.0839x; 1.0839x over previous
#include <cuda_runtime.h>
#include <cuda_bf16.h>
#include <math.h>
#include <stdint.h>
#include <string.h>

#define E   128
#define KC  12
#define BV  4096
#define RD  65536
#define NTILES 512
#define GRID_MAIN 128

#define LOG2PI  1.8378770664093453f
#define SQRT2C  1.4142135623730951f
#define SQRTPI  1.7724538509055159f

// ---------------- helpers ----------------
__device__ __forceinline__ uint32_t smem_u32(const void* p){
    uint32_t a;
    asm("{ .reg .u64 t; cvta.to.shared.u64 t, %1; cvt.u32.u64 %0, t; }" : "=r"(a) : "l"(p));
    return a;
}
#define LDS128(r0,r1,r2,r3,addr) \
    asm volatile("ld.shared.v4.b32 {%0,%1,%2,%3}, [%4];" \
        : "=r"(r0),"=r"(r1),"=r"(r2),"=r"(r3) : "r"(addr))
#define STS32(addr,v) \
    asm volatile("st.shared.b32 [%0], %1;" :: "r"(addr), "r"(v))
#define STS64F(addr,v0,v1) \
    asm volatile("st.shared.v2.f32 [%0], {%1,%2};" :: "r"(addr), "f"(v0), "f"(v1))
#define STS128(addr,r0,r1,r2,r3) \
    asm volatile("st.shared.v4.b32 [%0], {%1,%2,%3,%4};" \
        :: "r"(addr), "r"(r0),"r"(r1),"r"(r2),"r"(r3))

__device__ __forceinline__ void mma_bf16(float* d, uint32_t a0, uint32_t a1,
                                         uint32_t a2, uint32_t a3,
                                         uint32_t b0, uint32_t b1){
    asm("mma.sync.aligned.m16n8k16.row.col.f32.bf16.bf16.f32 "
        "{%0,%1,%2,%3}, {%4,%5,%6,%7}, {%8,%9}, {%0,%1,%2,%3};"
        : "+f"(d[0]), "+f"(d[1]), "+f"(d[2]), "+f"(d[3])
        : "r"(a0), "r"(a1), "r"(a2), "r"(a3), "r"(b0), "r"(b1));
}

__device__ __forceinline__ void split2(float v0, float v1, uint32_t& hb, uint32_t& lb){
    __nv_bfloat162 h = __float22bfloat162_rn(make_float2(v0, v1));
    float l0 = v0 - __bfloat162float(h.x);
    float l1 = v1 - __bfloat162float(h.y);
    __nv_bfloat162 lo = __float22bfloat162_rn(make_float2(l0, l1));
    memcpy(&hb, &h, 4);
    memcpy(&lb, &lo, 4);
}

// ---------------- smem layout ----------------
// A double-buffered: buf0 @ 0, buf1 @ 65536; each: AH 32KB + AL 32KB
#define A_L_OFF  32768
#define OFF_BH   131072    // 9 nb-pairs x 4096 = 36864
#define OFF_BL   167936    // 36864
#define OFF_DOT  204800    // 128 x 12 f32 = 6144
#define OFF_S2B  210944    // 3 x 128 f32 = 1536
#define OFF_NXB  212480    // 1536
#define OFF_SIG2 214016    // 512
#define OFF_T    214528    // 512
#define OFF_KON  215040    // 336
#define OFF_LSM  215376    // 48
#define ST_RED   215424    // 16
#define SMEM_BYTES 215552

// setup staging: DIRS aliases DOT; P aliases buf1 (first convert targets buf0)
#define ST_DIRS  OFF_DOT
#define ST_P     65536

__global__ void __launch_bounds__(768,1)
main_kernel(const float* __restrict__ alt,
            const float* __restrict__ trans,
            const float* __restrict__ rot,
            const float* __restrict__ stde,
            const float* __restrict__ dirs,
            const float* __restrict__ mu,
            const float* __restrict__ sig,
            const float* __restrict__ lam,
            const float* __restrict__ asd,
            const float* __restrict__ w,
            float* __restrict__ out)
{
    extern __shared__ char sm[];
    const uint32_t smb = smem_u32(sm);
    const int tid = threadIdx.x, wid = tid>>5, lane = tid&31;
    const int lq = lane>>2, lr = lane&3;
    const unsigned full = 0xffffffffu;
    float* SIG2f = (float*)(sm + OFF_SIG2);
    float* Tf    = (float*)(sm + OFF_T);
    float* KON   = (float*)(sm + OFF_KON);
    float* DOTf  = (float*)(sm + OFF_DOT);
    float* S2Bf  = (float*)(sm + OFF_S2B);
    float* NXBf  = (float*)(sm + OFF_NXB);
    float* LSM   = (float*)(sm + OFF_LSM);
    float* DIRSs = (float*)(sm + ST_DIRS);
    float* Ps    = (float*)(sm + ST_P);
    float* REDs  = (float*)(sm + ST_RED);

    // ======== setup phase 1 ========
    for (int i=tid; i<KC*E; i+=768) DIRSs[i] = dirs[i];

    float lv = 0.f;
    if (tid < E){
        float s = stde[tid];
        SIG2f[tid] = s*s;
        Tf[tid]    = trans[tid];
        lv = logf(s);
    }
    #pragma unroll
    for (int o=16;o>0;o>>=1) lv += __shfl_xor_sync(full, lv, o);
    if (tid < E && lane==0) REDs[wid] = lv;

    if (tid < KC){
        float m=mu[tid], s_=sig[tid], l=lam[tid], a=asd[tid];
        float A = m + l*s_*s_;
        KON[tid]    = A;
        KON[12+tid] = m + A;
        KON[24+tid] = 1.f/(SQRT2C*s_);
        KON[36+tid] = logf(0.5f*l);
        KON[48+tid] = 0.5f*l;
        KON[60+tid] = -0.5f*(float)(E-1)*LOG2PI - (float)(E-1)*logf(a);
        KON[72+tid] = 1.f/(2.f*a*a);
    }
    if (tid >= 32 && tid < 64){
        int t = tid - 32;
        float v = (t < KC) ? w[t] : -1e30f;
        float m = v;
        #pragma unroll
        for (int o=8;o>0;o>>=1) m = fmaxf(m, __shfl_xor_sync(full, m, o));
        float e = (t < KC) ? expf(v-m) : 0.f;
        #pragma unroll
        for (int o=8;o>0;o>>=1) e += __shfl_xor_sync(full, e, o);
        if (t < KC) LSM[t] = v - (m + logf(e));
    }
    __syncthreads();
    const float slog = REDs[0]+REDs[1]+REDs[2]+REDs[3];

    // P[e][k]: 6 groups x 2 dirs (768 threads)
    {
        const int gg = tid>>7, e = tid&127;
        float p0=0.f, p1=0.f, n0=0.f, n1=0.f;
        const float* d0 = DIRSs + (gg*2+0)*E;
        const float* d1 = DIRSs + (gg*2+1)*E;
        #pragma unroll 16
        for (int j=0; j<E; j++){
            float rv = __ldg(rot + j*E + e);
            float a0 = d0[j], a1 = d1[j];
            p0 = fmaf(rv, a0, p0);  n0 = fmaf(a0, a0, n0);
            p1 = fmaf(rv, a1, p1);  n1 = fmaf(a1, a1, n1);
        }
        Ps[e*12 + gg*2    ] = p0 * rsqrtf(n0);
        Ps[e*12 + gg*2 + 1] = p1 * rsqrtf(n1);
    }

    // mapping
    const int ms = wid&7, nt = wid>>3;   // MMA: rows ms*16..+15, nb third nt
    const float2* a2 = (const float2*)alt;

    // convert: 16 warps (wid>=8): w8 = row-group, kh = kb half
    auto convert = [&](int tile, uint32_t bufbase){
        const int cw = wid - 8;
        const int w8 = cw&7, kh = cw>>3;
        const uint32_t convBase = bufbase + (uint32_t)(w8*4096 + lane*16);
        const int row0 = tile*128 + w8*16 + lq;
        #pragma unroll
        for (int kk=0; kk<4; kk++){
            int kb = kh*4 + kk;
            int c0 = kb*16 + 2*lr, c1 = c0 + 8;
            float2 v00 = a2[(size_t)row0*64     + (c0>>1)];
            float2 v10 = a2[(size_t)(row0+8)*64 + (c0>>1)];
            float2 v01 = a2[(size_t)row0*64     + (c1>>1)];
            float2 v11 = a2[(size_t)(row0+8)*64 + (c1>>1)];
            float2 t0 = *(const float2*)(Tf + c0);
            float2 t1 = *(const float2*)(Tf + c1);
            uint32_t h0,l0,h1,l1,h2,l2,h3,l3;
            split2(v00.x+t0.x, v00.y+t0.y, h0, l0);
            split2(v10.x+t0.x, v10.y+t0.y, h1, l1);
            split2(v01.x+t1.x, v01.y+t1.y, h2, l2);
            split2(v11.x+t1.x, v11.y+t1.y, h3, l3);
            STS128(convBase + kb*512,           h0,h1,h2,h3);
            STS128(convBase + A_L_OFF + kb*512, l0,l1,l2,l3);
        }
    };

    // first convert overlaps B-fill latency (targets buf0; Ps lives in buf1)
    const int t0 = blockIdx.x*4;
    if (wid >= 8) convert(t0, smb);

    __syncthreads();   // Ps visible

    // B fill, uniform nb-pair layout (12 iters x 768)
    #pragma unroll
    for (int it=0; it<12; it++){
        int p = tid + it*768;
        int n = p>>6, k = (p&63)*2;
        float v0, v1;
        if (n < 128){
            float is = rsqrtf(SIG2f[n]);
            v0 = __ldg(rot + n*E+k)*is; v1 = __ldg(rot + n*E+k+1)*is;
        } else if (n < 140){
            int kc = n-128;
            v0 = Ps[k*KC + kc]; v1 = Ps[(k+1)*KC + kc];
        } else { v0 = 0.f; v1 = 0.f; }
        uint32_t hb, lb;
        split2(v0, v1, hb, lb);
        int nb = n>>3;
        int pr = nb>>1, which = nb&1;
        int l  = (n&7)*4 + ((k&7)>>1);
        int jB = (k>>3)&1;
        int kb = k>>4;
        uint32_t byteB = (uint32_t)(pr*4096 + kb*512 + l*16 + which*8 + jB*4);
        STS32(smb + OFF_BH + byteB, hb);
        STS32(smb + OFF_BL + byteB, lb);
    }
    // ======== end setup ========

    #pragma unroll 1
    for (int it=0; it<4; it++){
        __syncthreads();   // A(buf it&1) + B ready; prev DOT consumed

        const uint32_t aBase = smb + (uint32_t)((it&1)*65536 + ms*4096 + lane*16);
        const uint32_t bhBase = smb + OFF_BH + (uint32_t)(nt*3*4096 + lane*16);
        const uint32_t blBase = smb + OFF_BL + (uint32_t)(nt*3*4096 + lane*16);

        // ---- MMA: 3 terms, 1 m16 frag, N third (6 nb)
        float acc[6][4];
        #pragma unroll
        for (int i=0;i<6;i++){ acc[i][0]=0.f; acc[i][1]=0.f; acc[i][2]=0.f; acc[i][3]=0.f; }

        #pragma unroll
        for (int kb=0; kb<8; kb++){
            uint32_t ah[4], al[4];
            LDS128(ah[0],ah[1],ah[2],ah[3], aBase + kb*512);
            LDS128(al[0],al[1],al[2],al[3], aBase + A_L_OFF + kb*512);
            #pragma unroll
            for (int i=0; i<3; i++){
                uint32_t bh[4], bl[4];
                LDS128(bh[0],bh[1],bh[2],bh[3], bhBase + i*4096 + kb*512);
                LDS128(bl[0],bl[1],bl[2],bl[3], blBase + i*4096 + kb*512);
                mma_bf16(acc[2*i  ], ah[0],ah[1],ah[2],ah[3], bh[0],bh[1]);
                mma_bf16(acc[2*i  ], al[0],al[1],al[2],al[3], bh[0],bh[1]);
                mma_bf16(acc[2*i  ], ah[0],ah[1],ah[2],ah[3], bl[0],bl[1]);
                mma_bf16(acc[2*i+1], ah[0],ah[1],ah[2],ah[3], bh[2],bh[3]);
                mma_bf16(acc[2*i+1], al[0],al[1],al[2],al[3], bh[2],bh[3]);
                mma_bf16(acc[2*i+1], ah[0],ah[1],ah[2],ah[3], bl[2],bl[3]);
            }
        }

        // ---- extract
        float s2v[2]={0.f,0.f}, nxv[2]={0.f,0.f};
        #pragma unroll
        for (int j=0; j<6; j++){
            int nbG = nt*6 + j;
            if (nbG < 16){
                int col = nbG*8 + 2*lr;
                float g0 = SIG2f[col], g1 = SIG2f[col+1];
                float q;
                q = acc[j][0]*acc[j][0]; s2v[0]+=q; nxv[0]=fmaf(q,g0,nxv[0]);
                q = acc[j][1]*acc[j][1]; s2v[0]+=q; nxv[0]=fmaf(q,g1,nxv[0]);
                q = acc[j][2]*acc[j][2]; s2v[1]+=q; nxv[1]=fmaf(q,g0,nxv[1]);
                q = acc[j][3]*acc[j][3]; s2v[1]+=q; nxv[1]=fmaf(q,g1,nxv[1]);
            } else {
                int kc = (nbG-16)*8 + 2*lr;
                if (kc < 12){
                    int r0 = ms*16 + lq;
                    uint32_t dbase = smb + OFF_DOT;
                    STS64F(dbase + (uint32_t)((r0  )*48 + kc*4), acc[j][0], acc[j][1]);
                    STS64F(dbase + (uint32_t)((r0+8)*48 + kc*4), acc[j][2], acc[j][3]);
                }
            }
        }
        #pragma unroll
        for (int o=1;o<4;o<<=1){
            s2v[0] += __shfl_xor_sync(full, s2v[0], o);
            s2v[1] += __shfl_xor_sync(full, s2v[1], o);
            nxv[0] += __shfl_xor_sync(full, nxv[0], o);
            nxv[1] += __shfl_xor_sync(full, nxv[1], o);
        }
        if (lr < 2){
            int row = ms*16 + lr*8 + lq;
            S2Bf[nt*128 + row] = s2v[lr];
            NXBf[nt*128 + row] = nxv[lr];
        }
        __syncthreads();   // DOT/S2B/NXB ready; A buffer consumed

        if (wid >= 8){
            if (it < 3) convert(t0+it+1, smb + (uint32_t)(((it+1)&1)*65536));
        } else {
            // ---- epilogue + in-warp segment reduction (warp = 1 variant)
            const int r = tid>>1, h = tid&1;
            float s2 = S2Bf[r] + S2Bf[128+r] + S2Bf[256+r];
            float nx = NXBf[r] + NXBf[128+r] + NXBf[256+r];
            float nonart = -64.f*LOG2PI - slog - 0.5f*s2;
            const float* drow = DOTf + r*12;
            float art[6];
            #pragma unroll
            for (int kk=0; kk<6; kk++){
                int k = h*6 + kk;
                float dk    = drow[k];
                float orth2 = nx - dk*dk;
                float oll   = KON[60+k] - orth2*KON[72+k];
                float z     = (KON[k] - dk)*KON[24+k];
                float lec;
                if (z > 5.f){
                    float z2=z*z, z4=z2*z2, z6=z4*z2;
                    lec = -z2 - logf(z*SQRTPI)
                          + log1pf(-1.f/(2.f*z2) + 3.f/(4.f*z4) - 15.f/(8.f*z6));
                } else {
                    lec = logf(erfcf(z));
                }
                float par = KON[36+k] + lec + KON[48+k]*(KON[12+k] - 2.f*dk);
                art[kk] = oll + par;
            }
            #pragma unroll
            for (int o=2; o<32; o<<=1){
                nonart += __shfl_xor_sync(full, nonart, o);
                #pragma unroll
                for (int kk=0; kk<6; kk++)
                    art[kk] += __shfl_xor_sync(full, art[kk], o);
            }
            float vmax = -1e30f, vsum = 0.f;
            float av[6];
            #pragma unroll
            for (int kk=0; kk<6; kk++){
                av[kk] = art[kk] + LSM[h*6 + kk];
                vmax = fmaxf(vmax, av[kk]);
            }
            #pragma unroll
            for (int kk=0; kk<6; kk++) vsum += expf(av[kk] - vmax);
            float m_o = __shfl_xor_sync(full, vmax, 1);
            float s_o = __shfl_xor_sync(full, vsum, 1);
            float M = fmaxf(vmax, m_o);
            float S = vsum*expf(vmax-M) + s_o*expf(m_o-M);
            float lse = M + logf(S);

            if (lane < 2){
                const int b = (t0+it)*8 + wid;
                if (h == 0){
                    float logits = lse - nonart;
                    out[b] = 20.f*tanhf(logits*(1.f/20.f));
                    out[BV + b*(KC+1)] = nonart;
                    #pragma unroll
                    for (int kk=0; kk<6; kk++)
                        out[BV + b*(KC+1) + 1 + kk] = av[kk];
                } else {
                    #pragma unroll
                    for (int kk=0; kk<6; kk++)
                        out[BV + b*(KC+1) + 7 + kk] = av[kk];
                }
            }
        }
    }
}

// ---------------- launch ----------------
extern "C" void kernel_launch(void* const* d_in, const int* in_sizes, int n_in,
                              void* d_out, int out_size)
{
    const float* alt   = (const float*)d_in[0];
    // d_in[1] = ref_re: unused by the reference output
    const float* trans = (const float*)d_in[2];
    const float* rot   = (const float*)d_in[3];
    const float* stde  = (const float*)d_in[4];
    const float* dirs  = (const float*)d_in[5];
    const float* mu    = (const float*)d_in[6];
    const float* sig   = (const float*)d_in[7];
    const float* lam   = (const float*)d_in[8];
    const float* asd   = (const float*)d_in[9];
    const float* w     = (const float*)d_in[10];
    float* out = (float*)d_out;

    cudaFuncSetAttribute(main_kernel, cudaFuncAttributeMaxDynamicSharedMemorySize,
                         SMEM_BYTES);

    main_kernel<<<GRID_MAIN, 768, SMEM_BYTES>>>(alt, trans, rot, stde, dirs,
                                                mu, sig, lam, asd, w, out);
}

// round 16
// speedup vs baseline: 1.1894x; 1.0974x over previous
#include <cuda_runtime.h>
#include <cuda_bf16.h>
#include <math.h>
#include <stdint.h>
#include <string.h>

#define E   128
#define KC  12
#define BV  4096
#define RD  65536
#define NTILES 512          // 128-read tiles
#define GRID_MAIN 128

#define LOG2PI  1.8378770664093453f
#define SQRT2C  1.4142135623730951f
#define SQRTPI  1.7724538509055159f

// ---------------- helpers ----------------
__device__ __forceinline__ uint32_t smem_u32(const void* p){
    uint32_t a;
    asm("{ .reg .u64 t; cvta.to.shared.u64 t, %1; cvt.u32.u64 %0, t; }" : "=r"(a) : "l"(p));
    return a;
}
#define LDS128(r0,r1,r2,r3,addr) \
    asm volatile("ld.shared.v4.b32 {%0,%1,%2,%3}, [%4];" \
        : "=r"(r0),"=r"(r1),"=r"(r2),"=r"(r3) : "r"(addr))
#define LDS64(r0,r1,addr) \
    asm volatile("ld.shared.v2.b32 {%0,%1}, [%2];" : "=r"(r0),"=r"(r1) : "r"(addr))
#define STS32(addr,v) \
    asm volatile("st.shared.b32 [%0], %1;" :: "r"(addr), "r"(v))
#define STS64F(addr,v0,v1) \
    asm volatile("st.shared.v2.f32 [%0], {%1,%2};" :: "r"(addr), "f"(v0), "f"(v1))
#define STS128(addr,r0,r1,r2,r3) \
    asm volatile("st.shared.v4.b32 [%0], {%1,%2,%3,%4};" \
        :: "r"(addr), "r"(r0),"r"(r1),"r"(r2),"r"(r3))
#define BARG(id) asm volatile("bar.sync %0, 256;" :: "r"(id) : "memory")
#define PREFL2(p) asm volatile("prefetch.global.L2 [%0];" :: "l"(p))

__device__ __forceinline__ void mma_bf16(float* d, uint32_t a0, uint32_t a1,
                                         uint32_t a2, uint32_t a3,
                                         uint32_t b0, uint32_t b1){
    asm("mma.sync.aligned.m16n8k16.row.col.f32.bf16.bf16.f32 "
        "{%0,%1,%2,%3}, {%4,%5,%6,%7}, {%8,%9}, {%0,%1,%2,%3};"
        : "+f"(d[0]), "+f"(d[1]), "+f"(d[2]), "+f"(d[3])
        : "r"(a0), "r"(a1), "r"(a2), "r"(a3), "r"(b0), "r"(b1));
}

__device__ __forceinline__ void split2(float v0, float v1, uint32_t& hb, uint32_t& lb){
    __nv_bfloat162 h = __float22bfloat162_rn(make_float2(v0, v1));
    float l0 = v0 - __bfloat162float(h.x);
    float l1 = v1 - __bfloat162float(h.y);
    __nv_bfloat162 lo = __float22bfloat162_rn(make_float2(l0, l1));
    memcpy(&hb, &h, 4);
    memcpy(&lb, &lo, 4);
}

// ---------------- smem layout ----------------
#define A_L_OFF  32768
#define OFF_BH   131072
#define OFF_BL   167936
#define OFF_DOT  204800    // 2 groups x 128 x 12 f32 = 12288
#define OFF_S2B  217088    // 4096
#define OFF_NXB  221184    // 4096
#define OFF_SIG2 225280    // 512
#define OFF_T    225792    // 512
#define OFF_KON  226304    // 336
#define OFF_LSM  226640    // 48
#define ST_RED   226688    // 16
#define SMEM_BYTES 226944

// setup staging OFF the A buffers (aliases DOT / S2B+NXB; dead until first MMA)
#define ST_DIRS  OFF_DOT           // 6144 of 12288
#define ST_P     OFF_S2B           // 6144 of 8192 (spans S2B+NXB)

__global__ void __launch_bounds__(512,1)
main_kernel(const float* __restrict__ alt,
            const float* __restrict__ trans,
            const float* __restrict__ rot,
            const float* __restrict__ stde,
            const float* __restrict__ dirs,
            const float* __restrict__ mu,
            const float* __restrict__ sig,
            const float* __restrict__ lam,
            const float* __restrict__ asd,
            const float* __restrict__ w,
            float* __restrict__ out)
{
    extern __shared__ char sm[];
    const uint32_t smb = smem_u32(sm);
    const int tid = threadIdx.x, wid = tid>>5, lane = tid&31;
    const int lq = lane>>2, lr = lane&3;
    const unsigned full = 0xffffffffu;
    float* SIG2f = (float*)(sm + OFF_SIG2);
    float* Tf    = (float*)(sm + OFF_T);
    float* KON   = (float*)(sm + OFF_KON);
    float* DOTf  = (float*)(sm + OFF_DOT);
    float* S2Bf  = (float*)(sm + OFF_S2B);
    float* NXBf  = (float*)(sm + OFF_NXB);
    float* LSM   = (float*)(sm + OFF_LSM);
    float* DIRSs = (float*)(sm + ST_DIRS);
    float* Ps    = (float*)(sm + ST_P);
    float* REDs  = (float*)(sm + ST_RED);

    // group decomposition (needed early for convert)
    const int g  = wid>>3, gw = wid&7;
    const int ms = gw&3,  hf = gw>>2;
    const int barid = g + 1;

    const uint32_t Ag       = smb + (uint32_t)(g*65536);
    const uint32_t convBase = Ag + (uint32_t)(gw*4096 + lane*16);
    const uint32_t aBase    = Ag + (uint32_t)(ms*8192 + lane*16);
    const uint32_t bPairH   = smb + OFF_BH + (uint32_t)(hf*18432 + lane*16);
    const uint32_t bPairL   = smb + OFF_BL + (uint32_t)(hf*18432 + lane*16);
    const uint32_t b8H      = smb + OFF_BH + (uint32_t)(hf*18432 + 16384 + lane*8);
    const uint32_t b8L      = smb + OFF_BL + (uint32_t)(hf*18432 + 16384 + lane*8);

    const float2* a2 = (const float2*)alt;

    auto convert = [&](int tile){
        const int row0 = tile*128 + gw*16 + lq;
        #pragma unroll
        for (int kb=0; kb<8; kb++){
            int c0 = kb*16 + 2*lr, c1 = c0 + 8;
            float2 v00 = a2[(size_t)row0*64     + (c0>>1)];
            float2 v10 = a2[(size_t)(row0+8)*64 + (c0>>1)];
            float2 v01 = a2[(size_t)row0*64     + (c1>>1)];
            float2 v11 = a2[(size_t)(row0+8)*64 + (c1>>1)];
            float2 t0 = *(const float2*)(Tf + c0);
            float2 t1 = *(const float2*)(Tf + c1);
            uint32_t h0,l0,h1,l1,h2,l2,h3,l3;
            split2(v00.x+t0.x, v00.y+t0.y, h0, l0);
            split2(v10.x+t0.x, v10.y+t0.y, h1, l1);
            split2(v01.x+t1.x, v01.y+t1.y, h2, l2);
            split2(v11.x+t1.x, v11.y+t1.y, h3, l3);
            STS128(convBase + kb*512,           h0,h1,h2,h3);
            STS128(convBase + A_L_OFF + kb*512, l0,l1,l2,l3);
        }
    };

    // ======== setup ========
    for (int i=tid; i<KC*E; i+=512) DIRSs[i] = dirs[i];

    float lv = 0.f;
    if (tid < E){
        float s = stde[tid];
        SIG2f[tid] = s*s;
        Tf[tid]    = trans[tid];
        lv = logf(s);
    }
    #pragma unroll
    for (int o=16;o>0;o>>=1) lv += __shfl_xor_sync(full, lv, o);
    if (tid < E && lane==0) REDs[wid] = lv;

    if (tid < KC){
        float m=mu[tid], s_=sig[tid], l=lam[tid], a=asd[tid];
        float A = m + l*s_*s_;
        KON[tid]    = A;
        KON[12+tid] = m + A;
        KON[24+tid] = 1.f/(SQRT2C*s_);
        KON[36+tid] = logf(0.5f*l);
        KON[48+tid] = 0.5f*l;
        KON[60+tid] = -0.5f*(float)(E-1)*LOG2PI - (float)(E-1)*logf(a);
        KON[72+tid] = 1.f/(2.f*a*a);
    }
    if (tid >= 32 && tid < 64){
        int t = tid - 32;
        float v = (t < KC) ? w[t] : -1e30f;
        float m = v;
        #pragma unroll
        for (int o=8;o>0;o>>=1) m = fmaxf(m, __shfl_xor_sync(full, m, o));
        float e = (t < KC) ? expf(v-m) : 0.f;
        #pragma unroll
        for (int o=8;o>0;o>>=1) e += __shfl_xor_sync(full, e, o);
        if (t < KC) LSM[t] = v - (m + logf(e));
    }
    __syncthreads();
    const float slog = REDs[0]+REDs[1]+REDs[2]+REDs[3];

    // P[e][k] = (Rot^T dirs_k)[e] / ||dirs_k||   (touches all of rot -> warms L1/L2)
    {
        const int gg = tid>>7, e = tid&127;
        float p0=0.f, p1=0.f, p2=0.f;
        float n0=0.f, n1=0.f, n2=0.f;
        const float* d0 = DIRSs + (gg*3+0)*E;
        const float* d1 = DIRSs + (gg*3+1)*E;
        const float* d2 = DIRSs + (gg*3+2)*E;
        #pragma unroll 16
        for (int j=0; j<E; j++){
            float rv = __ldg(rot + j*E + e);
            float a0 = d0[j], a1 = d1[j], a2 = d2[j];
            p0 = fmaf(rv, a0, p0);  n0 = fmaf(a0, a0, n0);
            p1 = fmaf(rv, a1, p1);  n1 = fmaf(a1, a1, n1);
            p2 = fmaf(rv, a2, p2);  n2 = fmaf(a2, a2, n2);
        }
        Ps[e*12 + gg*3    ] = p0 * rsqrtf(n0);
        Ps[e*12 + gg*3 + 1] = p1 * rsqrtf(n1);
        Ps[e*12 + gg*3 + 2] = p2 * rsqrtf(n2);
    }

    // first tile conversion: DRAM burst issues now, hides under B-fill below
    const int t0 = blockIdx.x*4 + g*2;
    convert(t0);

    __syncthreads();   // Ps visible

    // B fill into PAIRED layout (fully unrolled; rot now L1-resident)
    #pragma unroll
    for (int it=0; it<18; it++){
        int p = tid + it*512;
        int n = p>>6, k = (p&63)*2;
        float v0, v1;
        if (n < 128){
            float is = rsqrtf(SIG2f[n]);
            v0 = __ldg(rot + n*E+k)*is; v1 = __ldg(rot + n*E+k+1)*is;
        } else if (n < 140){
            int kc = n-128;
            v0 = Ps[k*KC + kc]; v1 = Ps[(k+1)*KC + kc];
        } else { v0 = 0.f; v1 = 0.f; }
        uint32_t hb, lb;
        split2(v0, v1, hb, lb);
        int nb = n>>3;
        int hfb = (nb >= 9);
        int nbl = nb - 9*hfb;
        int l  = (n&7)*4 + ((k&7)>>1);
        int jB = (k>>3)&1;
        int kb = k>>4;
        uint32_t byteB;
        if (nbl < 8){
            int i = nbl>>1, which = nbl&1;
            byteB = (uint32_t)(hfb*18432 + i*4096 + kb*512 + l*16 + which*8 + jB*4);
        } else {
            byteB = (uint32_t)(hfb*18432 + 16384 + kb*256 + l*8 + jB*4);
        }
        STS32(smb + OFF_BH + byteB, hb);
        STS32(smb + OFF_BL + byteB, lb);
    }
    __syncthreads();   // setup complete; DOT/S2B staging reusable
    // ======== end setup ========

    int t = t0;
    #pragma unroll 1
    for (int it=0; it<2; it++){
        BARG(barid);   // A(t) ready in this group's buffer

        // L2 prefetch of NEXT tile's A region (zero-register, no scoreboard):
        // by convert(t+1) time these lines are L2 hits instead of cold DRAM.
        if (it == 0){
            const char* pb = (const char*)(alt + (size_t)(t+1)*128*E);
            int gt = (tid & 255);
            PREFL2(pb + gt*256);
            PREFL2(pb + gt*256 + 128);
        }

        // ---- MMA: 3 terms, 2 m16-frags per warp (rows ms*32..+31)
        float acc0[9][4], acc1[9][4];
        #pragma unroll
        for (int i=0;i<9;i++){
            acc0[i][0]=0.f;acc0[i][1]=0.f;acc0[i][2]=0.f;acc0[i][3]=0.f;
            acc1[i][0]=0.f;acc1[i][1]=0.f;acc1[i][2]=0.f;acc1[i][3]=0.f;
        }
        #pragma unroll
        for (int kb=0; kb<8; kb++){
            uint32_t ah0[4], ah1[4], al0[4], al1[4];
            LDS128(ah0[0],ah0[1],ah0[2],ah0[3], aBase + kb*512);
            LDS128(ah1[0],ah1[1],ah1[2],ah1[3], aBase + 4096 + kb*512);
            LDS128(al0[0],al0[1],al0[2],al0[3], aBase + A_L_OFF + kb*512);
            LDS128(al1[0],al1[1],al1[2],al1[3], aBase + A_L_OFF + 4096 + kb*512);
            #pragma unroll
            for (int i=0; i<4; i++){
                uint32_t bh[4], bl[4];
                LDS128(bh[0],bh[1],bh[2],bh[3], bPairH + i*4096 + kb*512);
                LDS128(bl[0],bl[1],bl[2],bl[3], bPairL + i*4096 + kb*512);
                mma_bf16(acc0[2*i  ], ah0[0],ah0[1],ah0[2],ah0[3], bh[0],bh[1]);
                mma_bf16(acc1[2*i  ], ah1[0],ah1[1],ah1[2],ah1[3], bh[0],bh[1]);
                mma_bf16(acc0[2*i  ], al0[0],al0[1],al0[2],al0[3], bh[0],bh[1]);
                mma_bf16(acc1[2*i  ], al1[0],al1[1],al1[2],al1[3], bh[0],bh[1]);
                mma_bf16(acc0[2*i  ], ah0[0],ah0[1],ah0[2],ah0[3], bl[0],bl[1]);
                mma_bf16(acc1[2*i  ], ah1[0],ah1[1],ah1[2],ah1[3], bl[0],bl[1]);
                mma_bf16(acc0[2*i+1], ah0[0],ah0[1],ah0[2],ah0[3], bh[2],bh[3]);
                mma_bf16(acc1[2*i+1], ah1[0],ah1[1],ah1[2],ah1[3], bh[2],bh[3]);
                mma_bf16(acc0[2*i+1], al0[0],al0[1],al0[2],al0[3], bh[2],bh[3]);
                mma_bf16(acc1[2*i+1], al1[0],al1[1],al1[2],al1[3], bh[2],bh[3]);
                mma_bf16(acc0[2*i+1], ah0[0],ah0[1],ah0[2],ah0[3], bl[2],bl[3]);
                mma_bf16(acc1[2*i+1], ah1[0],ah1[1],ah1[2],ah1[3], bl[2],bl[3]);
            }
            {
                uint32_t bh0,bh1,bl0,bl1;
                LDS64(bh0,bh1, b8H + kb*256);
                LDS64(bl0,bl1, b8L + kb*256);
                mma_bf16(acc0[8], ah0[0],ah0[1],ah0[2],ah0[3], bh0,bh1);
                mma_bf16(acc1[8], ah1[0],ah1[1],ah1[2],ah1[3], bh0,bh1);
                mma_bf16(acc0[8], al0[0],al0[1],al0[2],al0[3], bh0,bh1);
                mma_bf16(acc1[8], al1[0],al1[1],al1[2],al1[3], bh0,bh1);
                mma_bf16(acc0[8], ah0[0],ah0[1],ah0[2],ah0[3], bl0,bl1);
                mma_bf16(acc1[8], ah1[0],ah1[1],ah1[2],ah1[3], bl0,bl1);
            }
        }

        // ---- extract: s2/nx partials + dot columns
        float s2v[4]={0.f,0.f,0.f,0.f}, nxv[4]={0.f,0.f,0.f,0.f};
        #pragma unroll
        for (int nb=0; nb<9; nb++){
            int col = hf*72 + nb*8 + 2*lr;
            if (hf==0 || nb<7){
                float g0 = SIG2f[col], g1 = SIG2f[col+1];
                float q;
                q = acc0[nb][0]*acc0[nb][0]; s2v[0]+=q; nxv[0]=fmaf(q,g0,nxv[0]);
                q = acc0[nb][1]*acc0[nb][1]; s2v[0]+=q; nxv[0]=fmaf(q,g1,nxv[0]);
                q = acc0[nb][2]*acc0[nb][2]; s2v[1]+=q; nxv[1]=fmaf(q,g0,nxv[1]);
                q = acc0[nb][3]*acc0[nb][3]; s2v[1]+=q; nxv[1]=fmaf(q,g1,nxv[1]);
                q = acc1[nb][0]*acc1[nb][0]; s2v[2]+=q; nxv[2]=fmaf(q,g0,nxv[2]);
                q = acc1[nb][1]*acc1[nb][1]; s2v[2]+=q; nxv[2]=fmaf(q,g1,nxv[2]);
                q = acc1[nb][2]*acc1[nb][2]; s2v[3]+=q; nxv[3]=fmaf(q,g0,nxv[3]);
                q = acc1[nb][3]*acc1[nb][3]; s2v[3]+=q; nxv[3]=fmaf(q,g1,nxv[3]);
            } else {
                int kc = (nb-7)*8 + 2*lr;
                if (kc < 12){
                    int r0 = ms*32 + lq;
                    uint32_t dbase = smb + OFF_DOT + (uint32_t)(g*6144);
                    STS64F(dbase + (uint32_t)((r0   )*48 + kc*4), acc0[nb][0], acc0[nb][1]);
                    STS64F(dbase + (uint32_t)((r0+ 8)*48 + kc*4), acc0[nb][2], acc0[nb][3]);
                    STS64F(dbase + (uint32_t)((r0+16)*48 + kc*4), acc1[nb][0], acc1[nb][1]);
                    STS64F(dbase + (uint32_t)((r0+24)*48 + kc*4), acc1[nb][2], acc1[nb][3]);
                }
            }
        }
        #pragma unroll
        for (int o=1;o<4;o<<=1){
            #pragma unroll
            for (int i=0;i<4;i++){
                s2v[i] += __shfl_xor_sync(full, s2v[i], o);
                nxv[i] += __shfl_xor_sync(full, nxv[i], o);
            }
        }
        {
            float sv = (lr==0)?s2v[0]:(lr==1)?s2v[1]:(lr==2)?s2v[2]:s2v[3];
            float nv = (lr==0)?nxv[0]:(lr==1)?nxv[1]:(lr==2)?nxv[2]:nxv[3];
            int row = ms*32 + lr*8 + lq;
            S2Bf[(g*2+hf)*128 + row] = sv;
            NXBf[(g*2+hf)*128 + row] = nv;
        }
        BARG(barid);   // DOT/S2B/NXB ready; A buffer free

        if (it == 0) convert(t+1);   // LDGs now hit L2 (prefetched), overlap epilogue

        // ---- epilogue + in-warp segment reduction (warp = 1 variant of 16 reads)
        {
            const int gtid = tid & 255;
            const int r = gtid>>1, h = gtid&1;
            float s2 = S2Bf[(g*2)*128 + r] + S2Bf[(g*2+1)*128 + r];
            float nx = NXBf[(g*2)*128 + r] + NXBf[(g*2+1)*128 + r];
            float nonart = -64.f*LOG2PI - slog - 0.5f*s2;
            const float2* drow2 = (const float2*)(DOTf + g*1536 + r*12 + h*6);
            float2 d01 = drow2[0], d23 = drow2[1], d45 = drow2[2];
            float dkv[6] = {d01.x, d01.y, d23.x, d23.y, d45.x, d45.y};
            float art[6];
            #pragma unroll
            for (int kk=0; kk<6; kk++){
                int k = h*6 + kk;
                float dk    = dkv[kk];
                float orth2 = nx - dk*dk;
                float oll   = KON[60+k] - orth2*KON[72+k];
                float z     = (KON[k] - dk)*KON[24+k];
                float lec;
                if (z > 5.f){
                    float z2=z*z, z4=z2*z2, z6=z4*z2;
                    lec = -z2 - logf(z*SQRTPI)
                          + log1pf(-1.f/(2.f*z2) + 3.f/(4.f*z4) - 15.f/(8.f*z6));
                } else {
                    lec = logf(erfcf(z));
                }
                float par = KON[36+k] + lec + KON[48+k]*(KON[12+k] - 2.f*dk);
                art[kk] = oll + par;
            }
            #pragma unroll
            for (int o=2; o<32; o<<=1){
                nonart += __shfl_xor_sync(full, nonart, o);
                #pragma unroll
                for (int kk=0; kk<6; kk++)
                    art[kk] += __shfl_xor_sync(full, art[kk], o);
            }
            float vmax = -1e30f, vsum = 0.f;
            float av[6];
            #pragma unroll
            for (int kk=0; kk<6; kk++){
                av[kk] = art[kk] + LSM[h*6 + kk];
                vmax = fmaxf(vmax, av[kk]);
            }
            #pragma unroll
            for (int kk=0; kk<6; kk++) vsum += expf(av[kk] - vmax);
            float m_o = __shfl_xor_sync(full, vmax, 1);
            float s_o = __shfl_xor_sync(full, vsum, 1);
            float M = fmaxf(vmax, m_o);
            float S = vsum*expf(vmax-M) + s_o*expf(m_o-M);
            float lse = M + logf(S);

            if (lane < 2){
                const int b = t*8 + gw;
                if (h == 0){
                    float logits = lse - nonart;
                    out[b] = 20.f*tanhf(logits*(1.f/20.f));
                    out[BV + b*(KC+1)] = nonart;
                    #pragma unroll
                    for (int kk=0; kk<6; kk++)
                        out[BV + b*(KC+1) + 1 + kk] = av[kk];
                } else {
                    #pragma unroll
                    for (int kk=0; kk<6; kk++)
                        out[BV + b*(KC+1) + 7 + kk] = av[kk];
                }
            }
        }
        t++;
    }
}

// ---------------- launch ----------------
extern "C" void kernel_launch(void* const* d_in, const int* in_sizes, int n_in,
                              void* d_out, int out_size)
{
    const float* alt   = (const float*)d_in[0];
    // d_in[1] = ref_re: unused by the reference output
    const float* trans = (const float*)d_in[2];
    const float* rot   = (const float*)d_in[3];
    const float* stde  = (const float*)d_in[4];
    const float* dirs  = (const float*)d_in[5];
    const float* mu    = (const float*)d_in[6];
    const float* sig   = (const float*)d_in[7];
    const float* lam   = (const float*)d_in[8];
    const float* asd   = (const float*)d_in[9];
    const float* w     = (const float*)d_in[10];
    float* out = (float*)d_out;

    cudaFuncSetAttribute(main_kernel, cudaFuncAttributeMaxDynamicSharedMemorySize,
                         SMEM_BYTES);

    main_kernel<<<GRID_MAIN, 512, SMEM_BYTES>>>(alt, trans, rot, stde, dirs,
                                                mu, sig, lam, asd, w, out);
}

// round 17
// speedup vs baseline: 1.3824x; 1.1622x over previous
#include <cuda_runtime.h>
#include <cuda_bf16.h>
#include <math.h>
#include <stdint.h>
#include <string.h>

#define E   128
#define KC  12
#define BV  4096
#define RD  65536
#define NTILES 512          // 128-read tiles
#define GRID_MAIN 128

#define LOG2PI  1.8378770664093453f
#define SQRT2C  1.4142135623730951f
#define SQRTPI  1.7724538509055159f

// ---------------- helpers ----------------
__device__ __forceinline__ uint32_t smem_u32(const void* p){
    uint32_t a;
    asm("{ .reg .u64 t; cvta.to.shared.u64 t, %1; cvt.u32.u64 %0, t; }" : "=r"(a) : "l"(p));
    return a;
}
#define LDS128(r0,r1,r2,r3,addr) \
    asm volatile("ld.shared.v4.b32 {%0,%1,%2,%3}, [%4];" \
        : "=r"(r0),"=r"(r1),"=r"(r2),"=r"(r3) : "r"(addr))
#define LDS64(r0,r1,addr) \
    asm volatile("ld.shared.v2.b32 {%0,%1}, [%2];" : "=r"(r0),"=r"(r1) : "r"(addr))
#define STS32(addr,v) \
    asm volatile("st.shared.b32 [%0], %1;" :: "r"(addr), "r"(v))
#define STS64F(addr,v0,v1) \
    asm volatile("st.shared.v2.f32 [%0], {%1,%2};" :: "r"(addr), "f"(v0), "f"(v1))
#define STS128(addr,r0,r1,r2,r3) \
    asm volatile("st.shared.v4.b32 [%0], {%1,%2,%3,%4};" \
        :: "r"(addr), "r"(r0),"r"(r1),"r"(r2),"r"(r3))
#define BARG(id) asm volatile("bar.sync %0, 256;" :: "r"(id) : "memory")
#define PREFL2(p) asm volatile("prefetch.global.L2 [%0];" :: "l"(p))

__device__ __forceinline__ void mma_bf16(float* d, uint32_t a0, uint32_t a1,
                                         uint32_t a2, uint32_t a3,
                                         uint32_t b0, uint32_t b1){
    asm("mma.sync.aligned.m16n8k16.row.col.f32.bf16.bf16.f32 "
        "{%0,%1,%2,%3}, {%4,%5,%6,%7}, {%8,%9}, {%0,%1,%2,%3};"
        : "+f"(d[0]), "+f"(d[1]), "+f"(d[2]), "+f"(d[3])
        : "r"(a0), "r"(a1), "r"(a2), "r"(a3), "r"(b0), "r"(b1));
}

__device__ __forceinline__ void split2(float v0, float v1, uint32_t& hb, uint32_t& lb){
    __nv_bfloat162 h = __float22bfloat162_rn(make_float2(v0, v1));
    float l0 = v0 - __bfloat162float(h.x);
    float l1 = v1 - __bfloat162float(h.y);
    __nv_bfloat162 lo = __float22bfloat162_rn(make_float2(l0, l1));
    memcpy(&hb, &h, 4);
    memcpy(&lb, &lo, 4);
}
__device__ __forceinline__ uint32_t pack2(float v0, float v1){
    __nv_bfloat162 h = __float22bfloat162_rn(make_float2(v0, v1));
    uint32_t r; memcpy(&r, &h, 4); return r;
}

// ---------------- smem layout (A high-only: 2 groups x 32KB) ----------------
#define OFF_BH   65536     // 2 hf x (4 pairs x 4096 + 2048) = 36864
#define OFF_BL   102400    // 36864
#define OFF_DOT  139264    // 2 groups x 128 x 12 f32 = 12288
#define OFF_S2B  151552    // 4096
#define OFF_NXB  155648    // 4096
#define OFF_SIG2 159744    // 512
#define OFF_T    160256    // 512
#define OFF_KON  160768    // 336
#define OFF_LSM  161104    // 48
#define ST_RED   161152    // 16
#define SMEM_BYTES 161408

// setup staging OFF the A buffers (aliases DOT / S2B+NXB; dead until first MMA)
#define ST_DIRS  OFF_DOT           // 6144 of 12288
#define ST_P     OFF_S2B           // 6144 of 8192 (spans S2B+NXB)

__global__ void __launch_bounds__(512,1)
main_kernel(const float* __restrict__ alt,
            const float* __restrict__ trans,
            const float* __restrict__ rot,
            const float* __restrict__ stde,
            const float* __restrict__ dirs,
            const float* __restrict__ mu,
            const float* __restrict__ sig,
            const float* __restrict__ lam,
            const float* __restrict__ asd,
            const float* __restrict__ w,
            float* __restrict__ out)
{
    extern __shared__ char sm[];
    const uint32_t smb = smem_u32(sm);
    const int tid = threadIdx.x, wid = tid>>5, lane = tid&31;
    const int lq = lane>>2, lr = lane&3;
    const unsigned full = 0xffffffffu;
    float* SIG2f = (float*)(sm + OFF_SIG2);
    float* Tf    = (float*)(sm + OFF_T);
    float* KON   = (float*)(sm + OFF_KON);
    float* DOTf  = (float*)(sm + OFF_DOT);
    float* S2Bf  = (float*)(sm + OFF_S2B);
    float* NXBf  = (float*)(sm + OFF_NXB);
    float* LSM   = (float*)(sm + OFF_LSM);
    float* DIRSs = (float*)(sm + ST_DIRS);
    float* Ps    = (float*)(sm + ST_P);
    float* REDs  = (float*)(sm + ST_RED);

    // group decomposition
    const int g  = wid>>3, gw = wid&7;
    const int ms = gw&3,  hf = gw>>2;
    const int barid = g + 1;

    const uint32_t Ag       = smb + (uint32_t)(g*32768);
    const uint32_t convBase = Ag + (uint32_t)(gw*4096 + lane*16);
    const uint32_t aBase    = Ag + (uint32_t)(ms*8192 + lane*16);
    const uint32_t bPairH   = smb + OFF_BH + (uint32_t)(hf*18432 + lane*16);
    const uint32_t bPairL   = smb + OFF_BL + (uint32_t)(hf*18432 + lane*16);
    const uint32_t b8H      = smb + OFF_BH + (uint32_t)(hf*18432 + 16384 + lane*8);
    const uint32_t b8L      = smb + OFF_BL + (uint32_t)(hf*18432 + 16384 + lane*8);

    const float2* a2 = (const float2*)alt;

    // convert: A-high only (no residual) — 1 STS128 per kb
    auto convert = [&](int tile){
        const int row0 = tile*128 + gw*16 + lq;
        #pragma unroll
        for (int kb=0; kb<8; kb++){
            int c0 = kb*16 + 2*lr, c1 = c0 + 8;
            float2 v00 = a2[(size_t)row0*64     + (c0>>1)];
            float2 v10 = a2[(size_t)(row0+8)*64 + (c0>>1)];
            float2 v01 = a2[(size_t)row0*64     + (c1>>1)];
            float2 v11 = a2[(size_t)(row0+8)*64 + (c1>>1)];
            float2 t0 = *(const float2*)(Tf + c0);
            float2 t1 = *(const float2*)(Tf + c1);
            uint32_t h0 = pack2(v00.x+t0.x, v00.y+t0.y);
            uint32_t h1 = pack2(v10.x+t0.x, v10.y+t0.y);
            uint32_t h2 = pack2(v01.x+t1.x, v01.y+t1.y);
            uint32_t h3 = pack2(v11.x+t1.x, v11.y+t1.y);
            STS128(convBase + kb*512, h0,h1,h2,h3);
        }
    };

    // ======== setup ========
    for (int i=tid; i<KC*E; i+=512) DIRSs[i] = dirs[i];

    float lv = 0.f;
    if (tid < E){
        float s = stde[tid];
        SIG2f[tid] = s*s;
        Tf[tid]    = trans[tid];
        lv = logf(s);
    }
    #pragma unroll
    for (int o=16;o>0;o>>=1) lv += __shfl_xor_sync(full, lv, o);
    if (tid < E && lane==0) REDs[wid] = lv;

    if (tid < KC){
        float m=mu[tid], s_=sig[tid], l=lam[tid], a=asd[tid];
        float A = m + l*s_*s_;
        KON[tid]    = A;
        KON[12+tid] = m + A;
        KON[24+tid] = 1.f/(SQRT2C*s_);
        KON[36+tid] = logf(0.5f*l);
        KON[48+tid] = 0.5f*l;
        KON[60+tid] = -0.5f*(float)(E-1)*LOG2PI - (float)(E-1)*logf(a);
        KON[72+tid] = 1.f/(2.f*a*a);
    }
    if (tid >= 32 && tid < 64){
        int t = tid - 32;
        float v = (t < KC) ? w[t] : -1e30f;
        float m = v;
        #pragma unroll
        for (int o=8;o>0;o>>=1) m = fmaxf(m, __shfl_xor_sync(full, m, o));
        float e = (t < KC) ? expf(v-m) : 0.f;
        #pragma unroll
        for (int o=8;o>0;o>>=1) e += __shfl_xor_sync(full, e, o);
        if (t < KC) LSM[t] = v - (m + logf(e));
    }
    __syncthreads();
    const float slog = REDs[0]+REDs[1]+REDs[2]+REDs[3];

    // P[e][k] = (Rot^T dirs_k)[e] / ||dirs_k||   (touches all of rot -> warms L1/L2)
    {
        const int gg = tid>>7, e = tid&127;
        float p0=0.f, p1=0.f, p2=0.f;
        float n0=0.f, n1=0.f, n2=0.f;
        const float* d0 = DIRSs + (gg*3+0)*E;
        const float* d1 = DIRSs + (gg*3+1)*E;
        const float* d2 = DIRSs + (gg*3+2)*E;
        #pragma unroll 16
        for (int j=0; j<E; j++){
            float rv = __ldg(rot + j*E + e);
            float a0 = d0[j], a1 = d1[j], a2 = d2[j];
            p0 = fmaf(rv, a0, p0);  n0 = fmaf(a0, a0, n0);
            p1 = fmaf(rv, a1, p1);  n1 = fmaf(a1, a1, n1);
            p2 = fmaf(rv, a2, p2);  n2 = fmaf(a2, a2, n2);
        }
        Ps[e*12 + gg*3    ] = p0 * rsqrtf(n0);
        Ps[e*12 + gg*3 + 1] = p1 * rsqrtf(n1);
        Ps[e*12 + gg*3 + 2] = p2 * rsqrtf(n2);
    }

    // first tile conversion: DRAM burst issues now, hides under B-fill below
    const int t0 = blockIdx.x*4 + g*2;
    convert(t0);

    __syncthreads();   // Ps visible

    // B fill into PAIRED layout (fully unrolled; rot now L1-resident)
    #pragma unroll
    for (int it=0; it<18; it++){
        int p = tid + it*512;
        int n = p>>6, k = (p&63)*2;
        float v0, v1;
        if (n < 128){
            float is = rsqrtf(SIG2f[n]);
            v0 = __ldg(rot + n*E+k)*is; v1 = __ldg(rot + n*E+k+1)*is;
        } else if (n < 140){
            int kc = n-128;
            v0 = Ps[k*KC + kc]; v1 = Ps[(k+1)*KC + kc];
        } else { v0 = 0.f; v1 = 0.f; }
        uint32_t hb, lb;
        split2(v0, v1, hb, lb);
        int nb = n>>3;
        int hfb = (nb >= 9);
        int nbl = nb - 9*hfb;
        int l  = (n&7)*4 + ((k&7)>>1);
        int jB = (k>>3)&1;
        int kb = k>>4;
        uint32_t byteB;
        if (nbl < 8){
            int i = nbl>>1, which = nbl&1;
            byteB = (uint32_t)(hfb*18432 + i*4096 + kb*512 + l*16 + which*8 + jB*4);
        } else {
            byteB = (uint32_t)(hfb*18432 + 16384 + kb*256 + l*8 + jB*4);
        }
        STS32(smb + OFF_BH + byteB, hb);
        STS32(smb + OFF_BL + byteB, lb);
    }
    __syncthreads();   // setup complete; DOT/S2B staging reusable
    // ======== end setup ========

    int t = t0;
    #pragma unroll 1
    for (int it=0; it<2; it++){
        BARG(barid);   // A(t) ready in this group's buffer

        // L2 prefetch of NEXT tile's A region
        if (it == 0){
            const char* pb = (const char*)(alt + (size_t)(t+1)*128*E);
            int gt = (tid & 255);
            PREFL2(pb + gt*256);
            PREFL2(pb + gt*256 + 128);
        }

        // ---- MMA: 2 terms (ah*Bh + ah*Bl), 2 m16-frags per warp
        float acc0[9][4], acc1[9][4];
        #pragma unroll
        for (int i=0;i<9;i++){
            acc0[i][0]=0.f;acc0[i][1]=0.f;acc0[i][2]=0.f;acc0[i][3]=0.f;
            acc1[i][0]=0.f;acc1[i][1]=0.f;acc1[i][2]=0.f;acc1[i][3]=0.f;
        }
        #pragma unroll
        for (int kb=0; kb<8; kb++){
            uint32_t ah0[4], ah1[4];
            LDS128(ah0[0],ah0[1],ah0[2],ah0[3], aBase + kb*512);
            LDS128(ah1[0],ah1[1],ah1[2],ah1[3], aBase + 4096 + kb*512);
            #pragma unroll
            for (int i=0; i<4; i++){
                uint32_t bh[4], bl[4];
                LDS128(bh[0],bh[1],bh[2],bh[3], bPairH + i*4096 + kb*512);
                LDS128(bl[0],bl[1],bl[2],bl[3], bPairL + i*4096 + kb*512);
                mma_bf16(acc0[2*i  ], ah0[0],ah0[1],ah0[2],ah0[3], bh[0],bh[1]);
                mma_bf16(acc1[2*i  ], ah1[0],ah1[1],ah1[2],ah1[3], bh[0],bh[1]);
                mma_bf16(acc0[2*i  ], ah0[0],ah0[1],ah0[2],ah0[3], bl[0],bl[1]);
                mma_bf16(acc1[2*i  ], ah1[0],ah1[1],ah1[2],ah1[3], bl[0],bl[1]);
                mma_bf16(acc0[2*i+1], ah0[0],ah0[1],ah0[2],ah0[3], bh[2],bh[3]);
                mma_bf16(acc1[2*i+1], ah1[0],ah1[1],ah1[2],ah1[3], bh[2],bh[3]);
                mma_bf16(acc0[2*i+1], ah0[0],ah0[1],ah0[2],ah0[3], bl[2],bl[3]);
                mma_bf16(acc1[2*i+1], ah1[0],ah1[1],ah1[2],ah1[3], bl[2],bl[3]);
            }
            {
                uint32_t bh0,bh1,bl0,bl1;
                LDS64(bh0,bh1, b8H + kb*256);
                LDS64(bl0,bl1, b8L + kb*256);
                mma_bf16(acc0[8], ah0[0],ah0[1],ah0[2],ah0[3], bh0,bh1);
                mma_bf16(acc1[8], ah1[0],ah1[1],ah1[2],ah1[3], bh0,bh1);
                mma_bf16(acc0[8], ah0[0],ah0[1],ah0[2],ah0[3], bl0,bl1);
                mma_bf16(acc1[8], ah1[0],ah1[1],ah1[2],ah1[3], bl0,bl1);
            }
        }

        // ---- extract: s2/nx partials + dot columns
        float s2v[4]={0.f,0.f,0.f,0.f}, nxv[4]={0.f,0.f,0.f,0.f};
        #pragma unroll
        for (int nb=0; nb<9; nb++){
            int col = hf*72 + nb*8 + 2*lr;
            if (hf==0 || nb<7){
                float g0 = SIG2f[col], g1 = SIG2f[col+1];
                float q;
                q = acc0[nb][0]*acc0[nb][0]; s2v[0]+=q; nxv[0]=fmaf(q,g0,nxv[0]);
                q = acc0[nb][1]*acc0[nb][1]; s2v[0]+=q; nxv[0]=fmaf(q,g1,nxv[0]);
                q = acc0[nb][2]*acc0[nb][2]; s2v[1]+=q; nxv[1]=fmaf(q,g0,nxv[1]);
                q = acc0[nb][3]*acc0[nb][3]; s2v[1]+=q; nxv[1]=fmaf(q,g1,nxv[1]);
                q = acc1[nb][0]*acc1[nb][0]; s2v[2]+=q; nxv[2]=fmaf(q,g0,nxv[2]);
                q = acc1[nb][1]*acc1[nb][1]; s2v[2]+=q; nxv[2]=fmaf(q,g1,nxv[2]);
                q = acc1[nb][2]*acc1[nb][2]; s2v[3]+=q; nxv[3]=fmaf(q,g0,nxv[3]);
                q = acc1[nb][3]*acc1[nb][3]; s2v[3]+=q; nxv[3]=fmaf(q,g1,nxv[3]);
            } else {
                int kc = (nb-7)*8 + 2*lr;
                if (kc < 12){
                    int r0 = ms*32 + lq;
                    uint32_t dbase = smb + OFF_DOT + (uint32_t)(g*6144);
                    STS64F(dbase + (uint32_t)((r0   )*48 + kc*4), acc0[nb][0], acc0[nb][1]);
                    STS64F(dbase + (uint32_t)((r0+ 8)*48 + kc*4), acc0[nb][2], acc0[nb][3]);
                    STS64F(dbase + (uint32_t)((r0+16)*48 + kc*4), acc1[nb][0], acc1[nb][1]);
                    STS64F(dbase + (uint32_t)((r0+24)*48 + kc*4), acc1[nb][2], acc1[nb][3]);
                }
            }
        }
        #pragma unroll
        for (int o=1;o<4;o<<=1){
            #pragma unroll
            for (int i=0;i<4;i++){
                s2v[i] += __shfl_xor_sync(full, s2v[i], o);
                nxv[i] += __shfl_xor_sync(full, nxv[i], o);
            }
        }
        {
            float sv = (lr==0)?s2v[0]:(lr==1)?s2v[1]:(lr==2)?s2v[2]:s2v[3];
            float nv = (lr==0)?nxv[0]:(lr==1)?nxv[1]:(lr==2)?nxv[2]:nxv[3];
            int row = ms*32 + lr*8 + lq;
            S2Bf[(g*2+hf)*128 + row] = sv;
            NXBf[(g*2+hf)*128 + row] = nv;
        }
        BARG(barid);   // DOT/S2B/NXB ready; A buffer free

        if (it == 0) convert(t+1);   // LDGs hit L2 (prefetched), overlap epilogue

        // ---- epilogue + in-warp segment reduction (warp = 1 variant of 16 reads)
        {
            const int gtid = tid & 255;
            const int r = gtid>>1, h = gtid&1;
            float s2 = S2Bf[(g*2)*128 + r] + S2Bf[(g*2+1)*128 + r];
            float nx = NXBf[(g*2)*128 + r] + NXBf[(g*2+1)*128 + r];
            float nonart = -64.f*LOG2PI - slog - 0.5f*s2;
            const float2* drow2 = (const float2*)(DOTf + g*1536 + r*12 + h*6);
            float2 d01 = drow2[0], d23 = drow2[1], d45 = drow2[2];
            float dkv[6] = {d01.x, d01.y, d23.x, d23.y, d45.x, d45.y};
            float art[6];
            #pragma unroll
            for (int kk=0; kk<6; kk++){
                int k = h*6 + kk;
                float dk    = dkv[kk];
                float orth2 = nx - dk*dk;
                float oll   = KON[60+k] - orth2*KON[72+k];
                float z     = (KON[k] - dk)*KON[24+k];
                float lec;
                if (z > 5.f){
                    float z2=z*z, z4=z2*z2, z6=z4*z2;
                    lec = -z2 - logf(z*SQRTPI)
                          + log1pf(-1.f/(2.f*z2) + 3.f/(4.f*z4) - 15.f/(8.f*z6));
                } else {
                    lec = logf(erfcf(z));
                }
                float par = KON[36+k] + lec + KON[48+k]*(KON[12+k] - 2.f*dk);
                art[kk] = oll + par;
            }
            #pragma unroll
            for (int o=2; o<32; o<<=1){
                nonart += __shfl_xor_sync(full, nonart, o);
                #pragma unroll
                for (int kk=0; kk<6; kk++)
                    art[kk] += __shfl_xor_sync(full, art[kk], o);
            }
            float vmax = -1e30f, vsum = 0.f;
            float av[6];
            #pragma unroll
            for (int kk=0; kk<6; kk++){
                av[kk] = art[kk] + LSM[h*6 + kk];
                vmax = fmaxf(vmax, av[kk]);
            }
            #pragma unroll
            for (int kk=0; kk<6; kk++) vsum += expf(av[kk] - vmax);
            float m_o = __shfl_xor_sync(full, vmax, 1);
            float s_o = __shfl_xor_sync(full, vsum, 1);
            float M = fmaxf(vmax, m_o);
            float S = vsum*expf(vmax-M) + s_o*expf(m_o-M);
            float lse = M + logf(S);

            if (lane < 2){
                const int b = t*8 + gw;
                if (h == 0){
                    float logits = lse - nonart;
                    out[b] = 20.f*tanhf(logits*(1.f/20.f));
                    out[BV + b*(KC+1)] = nonart;
                    #pragma unroll
                    for (int kk=0; kk<6; kk++)
                        out[BV + b*(KC+1) + 1 + kk] = av[kk];
                } else {
                    #pragma unroll
                    for (int kk=0; kk<6; kk++)
                        out[BV + b*(KC+1) + 7 + kk] = av[kk];
                }
            }
        }
        t++;
    }
}

// ---------------- launch ----------------
extern "C" void kernel_launch(void* const* d_in, const int* in_sizes, int n_in,
                              void* d_out, int out_size)
{
    const float* alt   = (const float*)d_in[0];
    // d_in[1] = ref_re: unused by the reference output
    const float* trans = (const float*)d_in[2];
    const float* rot   = (const float*)d_in[3];
    const float* stde  = (const float*)d_in[4];
    const float* dirs  = (const float*)d_in[5];
    const float* mu    = (const float*)d_in[6];
    const float* sig   = (const float*)d_in[7];
    const float* lam   = (const float*)d_in[8];
    const float* asd   = (const float*)d_in[9];
    const float* w     = (const float*)d_in[10];
    float* out = (float*)d_out;

    cudaFuncSetAttribute(main_kernel, cudaFuncAttributeMaxDynamicSharedMemorySize,
                         SMEM_BYTES);

    main_kernel<<<GRID_MAIN, 512, SMEM_BYTES>>>(alt, trans, rot, stde, dirs,
                                                mu, sig, lam, asd, w, out);
}